// round 16
// baseline (speedup 1.0000x reference)
#include <cuda_runtime.h>
#include <cuda_fp16.h>
#include <math.h>
#include <string.h>
#include <stdint.h>

// Problem constants (fixed by the dataset)
#define MAX_E 500000
#define MAX_V 50000

// Scratch (allocation-free rule: __device__ globals)
static __device__ __align__(16) unsigned char g_P8[(size_t)MAX_V * 256]; // e4m3: emb@W_top + xi_b
static __device__ __align__(16) unsigned char g_Q8[(size_t)MAX_V * 256]; // e4m3: emb@W_bot
static __device__ __align__(16) unsigned char g_A8[(size_t)MAX_E * 256]; // e4m3: tanh(P+Q) per edge
static __device__ __half g_Eh[(size_t)MAX_V * 128]; // fp16 emb
static __device__ uint2  g_Wfrag[16384];            // xi_w in mma B-fragment order
static __device__ float  g_R[MAX_V * 16];           // tanh(emb @ rou_w + rou_b)
static __device__ float  g_s0[MAX_V * 16];
static __device__ float  g_s1[MAX_V * 16];
static __device__ float  g_s2[MAX_V * 16];

// Bit-cast helpers
__device__ __forceinline__ __half2 u32_as_h2(uint32_t u) {
    __half2 h; memcpy(&h, &u, 4); return h;
}
// 2 x e4m3 (packed u16, low byte = first value) -> half2 (low half = first value)
__device__ __forceinline__ __half2 fp8x2_to_h2(unsigned short u) {
    uint32_t r;
    asm("cvt.rn.f16x2.e4m3x2 %0, %1;" : "=r"(r) : "h"(u));
    return u32_as_h2(r);
}
// pack (lo, hi) floats -> e4m3x2 u16 (first PTX src -> upper byte)
__device__ __forceinline__ unsigned short f2_to_fp8x2(float lo, float hi) {
    unsigned short r;
    asm("cvt.rn.satfinite.e4m3x2.f32 %0, %1, %2;" : "=h"(r) : "f"(hi), "f"(lo));
    return r;
}

// ---------------------------------------------------------------------------
// Fast tanh (scalar): odd deg-13 poly for |x|<=0.8; tanhf fallback.
// ---------------------------------------------------------------------------
__device__ __forceinline__ float tanh_fast(float x) {
    float t = x * x;
    if (t > 0.64f) return tanhf(x);
    float p = 3.5921280e-3f;
    p = fmaf(p, t, -8.8632355e-3f);
    p = fmaf(p, t,  2.1869489e-2f);
    p = fmaf(p, t, -5.3968254e-2f);
    p = fmaf(p, t,  1.3333334e-1f);
    p = fmaf(p, t, -3.3333334e-1f);
    p = fmaf(p, t,  1.0f);
    return x * p;
}

// ---------------------------------------------------------------------------
// Packed f32x2 helpers
// ---------------------------------------------------------------------------
typedef unsigned long long u64t;
__device__ __forceinline__ u64t pack2(float a, float b) {
    u64t r; asm("mov.b64 %0, {%1, %2};" : "=l"(r) : "f"(a), "f"(b)); return r;
}
__device__ __forceinline__ void unpack2(u64t v, float& a, float& b) {
    asm("mov.b64 {%0, %1}, %2;" : "=f"(a), "=f"(b) : "l"(v));
}
__device__ __forceinline__ void fma2_acc(u64t& d, u64t a, u64t b) {
    asm("fma.rn.f32x2 %0, %1, %2, %0;" : "+l"(d) : "l"(a), "l"(b));
}
__device__ __forceinline__ u64t fma2(u64t a, u64t b, u64t c) {
    u64t d; asm("fma.rn.f32x2 %0, %1, %2, %3;" : "=l"(d) : "l"(a), "l"(b), "l"(c)); return d;
}
__device__ __forceinline__ u64t mul2(u64t a, u64t b) {
    u64t d; asm("mul.rn.f32x2 %0, %1, %2;" : "=l"(d) : "l"(a), "l"(b)); return d;
}

// m16n8k16 f16 HMMA with f32 accumulators
__device__ __forceinline__ void mma16816(float* d, uint32_t a0, uint32_t a1,
                                         uint32_t a2, uint32_t a3,
                                         uint32_t b0, uint32_t b1) {
    asm volatile(
        "mma.sync.aligned.m16n8k16.row.col.f32.f16.f16.f32 "
        "{%0,%1,%2,%3}, {%4,%5,%6,%7}, {%8,%9}, {%0,%1,%2,%3};"
        : "+f"(d[0]), "+f"(d[1]), "+f"(d[2]), "+f"(d[3])
        : "r"(a0), "r"(a1), "r"(a2), "r"(a3), "r"(b0), "r"(b1));
}

// ---------------------------------------------------------------------------
// k_prep: emb -> fp16 g_Eh, xi_w -> fragment-ordered g_Wfrag.
// ---------------------------------------------------------------------------
static __global__ void k_prep(const float* __restrict__ emb,
                              const float* __restrict__ xiw, int V)
{
    int idx = blockIdx.x * 256 + threadIdx.x;
    int ne2 = V * 64;                 // half2 count of emb
    if (idx < ne2) {
        float2 f = ((const float2*)emb)[idx];
        ((__half2*)g_Eh)[idx] = __floats2half2_rn(f.x, f.y);
    }
    int widx = idx - ne2;
    if (widx >= 0 && widx < 16384) {
        int t  = widx & 31;
        int nt = (widx >> 5) & 31;
        int ks = (widx >> 10) & 7;
        int hf = widx >> 13;
        int n  = nt * 8 + (t >> 2);
        int k0 = hf * 128 + ks * 16 + 2 * (t & 3);
        uint32_t h0 = __half_as_ushort(__float2half_rn(xiw[(k0    ) * 256 + n]));
        uint32_t h1 = __half_as_ushort(__float2half_rn(xiw[(k0 + 1) * 256 + n]));
        uint32_t h2 = __half_as_ushort(__float2half_rn(xiw[(k0 + 8) * 256 + n]));
        uint32_t h3 = __half_as_ushort(__float2half_rn(xiw[(k0 + 9) * 256 + n]));
        g_Wfrag[widx] = make_uint2(h0 | (h1 << 16), h2 | (h3 << 16));
    }
}

// ---------------------------------------------------------------------------
// K1 mega-kernel, role by blockIdx.x:
//   [0, NG)      node GEMM via mma.sync: P/Q fp8 out (64 nodes x 256 cols/blk)
//   [NG, 2NG)    R = tanh(emb @ rou_w + rou_b), 64 nodes/block
//   [2NG, +NZB)  zero s0, s1, s2
// ---------------------------------------------------------------------------
#define NZB 192
#define EPITCH 136

static __global__ __launch_bounds__(256, 2)
void k_pre(const float* __restrict__ emb, const float* __restrict__ xib,
           const float* __restrict__ rw, const float* __restrict__ rbias,
           int V, int NG)
{
    __shared__ __half XsT16[64 * EPITCH];
    __shared__ float rwT[16 * 132];
    const int tid = threadIdx.x;
    const int bid = blockIdx.x;

    if (bid < NG) {
        // ---------------- GEMM role (tensor core) ----------------
        const int v0 = bid * 64;
        for (int i = tid; i < 2048; i += 256) {
            int r = i >> 5, c4 = i & 31;
            int v = v0 + r;
            uint2 val = make_uint2(0u, 0u);
            if (v < V) val = *(const uint2*)(g_Eh + (size_t)v * 128 + c4 * 4);
            *(uint2*)(XsT16 + r * EPITCH + c4 * 4) = val;
        }
        __syncthreads();

        const int wid = tid >> 5, t = tid & 31;
        const int ng = wid & 3;
        const int ch = wid >> 2;
        const int r  = t >> 2, qt = t & 3;
        const __half* arow0 = XsT16 + (ng * 16 + r) * EPITCH;
        const __half* arow8 = arow0 + 8 * EPITCH;
        const int va = v0 + ng * 16 + r;
        const int vb = va + 8;

        #pragma unroll 1
        for (int half = 0; half < 2; ++half) {
            float d[16][4];
            #pragma unroll
            for (int j = 0; j < 16; ++j)
                { d[j][0] = d[j][1] = d[j][2] = d[j][3] = 0.f; }

            #pragma unroll
            for (int ks = 0; ks < 8; ++ks) {
                const int cofs = ks * 16 + 2 * qt;
                uint32_t a0 = *(const uint32_t*)(arow0 + cofs);
                uint32_t a1 = *(const uint32_t*)(arow8 + cofs);
                uint32_t a2 = *(const uint32_t*)(arow0 + cofs + 8);
                uint32_t a3 = *(const uint32_t*)(arow8 + cofs + 8);
                const uint2* base = g_Wfrag + (((half * 8 + ks) * 32 + ch * 16) * 32) + t;
                #pragma unroll
                for (int j = 0; j < 16; ++j) {
                    uint2 b = __ldg(base + j * 32);
                    mma16816(d[j], a0, a1, a2, a3, b.x, b.y);
                }
            }

            unsigned char* dst = half ? g_Q8 : g_P8;
            #pragma unroll
            for (int j = 0; j < 16; ++j) {
                const int n0 = (ch * 16 + j) * 8 + 2 * qt;
                float bx = 0.f, by = 0.f;
                if (half == 0) { bx = __ldg(&xib[n0]); by = __ldg(&xib[n0 + 1]); }
                if (va < V)
                    *(unsigned short*)(dst + (size_t)va * 256 + n0) =
                        f2_to_fp8x2(d[j][0] + bx, d[j][1] + by);
                if (vb < V)
                    *(unsigned short*)(dst + (size_t)vb * 256 + n0) =
                        f2_to_fp8x2(d[j][2] + bx, d[j][3] + by);
            }
        }
    } else if (bid < 2 * NG) {
        // ---------------- R role: 64 nodes per block ----------------
        for (int idx = tid; idx < 2048; idx += 256) {
            int k = idx >> 4, j = idx & 15;
            rwT[j * 132 + k] = rw[idx];
        }
        __syncthreads();
        const int base = (bid - NG) * 64;
        const int j = tid & 15;
        const float* wr = rwT + j * 132;
        #pragma unroll 1
        for (int pass = 0; pass < 4; ++pass) {
            int v = base + pass * 16 + (tid >> 4);
            if (v >= V) continue;
            const float* er = emb + (size_t)v * 128;
            float acc = __ldg(&rbias[j]);
            #pragma unroll
            for (int k = 0; k < 128; k += 4) {
                float4 xv = __ldg((const float4*)(er + k));
                float4 wv = *(const float4*)(wr + k);
                acc = fmaf(xv.x, wv.x, acc);
                acc = fmaf(xv.y, wv.y, acc);
                acc = fmaf(xv.z, wv.z, acc);
                acc = fmaf(xv.w, wv.w, acc);
            }
            g_R[v * 16 + j] = tanh_fast(acc);
        }
    } else {
        // ---------------- zero role: s0, s1, s2 ----------------
        const int n4 = (V * 16) / 4;
        const int stride = NZB * 256;
        float4 z = make_float4(0.f, 0.f, 0.f, 0.f);
        for (int i = (bid - 2 * NG) * 256 + tid; i < n4; i += stride) {
            ((float4*)g_s0)[i] = z;
            ((float4*)g_s1)[i] = z;
            ((float4*)g_s2)[i] = z;
        }
    }
}

// ---------------------------------------------------------------------------
// Step 1 (states=0 => H=R[src]): scatter-add R[src] into s0.
// 4 threads/edge, float4 load + red.global.add.v4.
// ---------------------------------------------------------------------------
static __global__ void k_prop_first(const int* __restrict__ Xn,
                                    const int* __restrict__ Xe, int E) {
    int idx = blockIdx.x * blockDim.x + threadIdx.x;
    if (idx >= E * 4) return;
    int e = idx >> 2, sq = (idx & 3) * 4;
    int src = __ldg(&Xn[e]);
    int nbr = __ldg(&Xe[e]);
    float4 r = __ldg((const float4*)(g_R + src * 16 + sq));
    float* dst = g_s0 + nbr * 16 + sq;
    asm volatile("red.global.add.v4.f32 [%0], {%1,%2,%3,%4};"
                 :: "l"(dst), "f"(r.x), "f"(r.y), "f"(r.z), "f"(r.w) : "memory");
}

// ---------------------------------------------------------------------------
// Step 2: s0 -> s1, A recomputed from fp8 P/Q; tanh values ALSO stored to
// g_A8 (e4m3, pre-scale) so step 3 can stream them without recomputing.
// ---------------------------------------------------------------------------
static __global__ __launch_bounds__(256, 5)
void k_prop_store(const int* __restrict__ Xn, const int* __restrict__ Xe,
                  const int* __restrict__ dg, int E)
{
    int idx = blockIdx.x * 256 + threadIdx.x;
    int e = idx >> 4, s = idx & 15;
    if (e >= E) return;

    const int src = __ldg(&Xn[e]);
    const int nbr = __ldg(&Xe[e]);

    const uint4 pu = __ldg((const uint4*)(g_P8 + (size_t)src * 256 + s * 16));
    const uint4 qu = __ldg((const uint4*)(g_Q8 + (size_t)nbr * 256 + s * 16));
    const float h   = __ldg(&g_s0[src * 16 + s]);
    const float rsv = __ldg(&g_R[src * 16 + s]);
    const float sc  = __fdividef(0.05625f, (float)__ldg(&dg[e]));

    u64t hp[8];
    #pragma unroll
    for (int j = 0; j < 8; ++j) {
        float ha = __shfl_sync(0xffffffffu, h, 2 * j,     16);
        float hb = __shfl_sync(0xffffffffu, h, 2 * j + 1, 16);
        hp[j] = pack2(ha, hb);
    }

    const uint32_t pw[4] = { pu.x, pu.y, pu.z, pu.w };
    const uint32_t qw[4] = { qu.x, qu.y, qu.z, qu.w };
    __half2 sv[8];
    #pragma unroll
    for (int w = 0; w < 4; ++w) {
        sv[2 * w]     = __hadd2(fp8x2_to_h2((unsigned short)(pw[w] & 0xFFFFu)),
                                fp8x2_to_h2((unsigned short)(qw[w] & 0xFFFFu)));
        sv[2 * w + 1] = __hadd2(fp8x2_to_h2((unsigned short)(pw[w] >> 16)),
                                fp8x2_to_h2((unsigned short)(qw[w] >> 16)));
    }

    __half2 m = __habs2(sv[0]);
    #pragma unroll
    for (int j = 1; j < 8; ++j) m = __hmax2(m, __habs2(sv[j]));
    const float mx = fmaxf(__low2float(m), __high2float(m));

    u64t acc2 = 0ull;
    unsigned short c8[8];
    if (__builtin_expect(mx <= 0.6f, 1)) {
        const u64t c3 = pack2(-5.3968254e-2f, -5.3968254e-2f);
        const u64t c2 = pack2( 1.3333334e-1f,  1.3333334e-1f);
        const u64t c1 = pack2(-3.3333334e-1f, -3.3333334e-1f);
        const u64t c0 = pack2( 1.0f, 1.0f);
        #pragma unroll
        for (int j = 0; j < 8; ++j) {
            float2 f = __half22float2(sv[j]);
            u64t x = pack2(f.x, f.y);
            u64t t = mul2(x, x);
            u64t p = fma2(c3, t, c2);
            p = fma2(p, t, c1);
            p = fma2(p, t, c0);
            u64t tv = mul2(x, p);
            fma2_acc(acc2, tv, hp[j]);
            float ta, tb;
            unpack2(tv, ta, tb);
            c8[j] = f2_to_fp8x2(ta, tb);
        }
    } else {
        #pragma unroll
        for (int j = 0; j < 8; ++j) {
            float2 f = __half22float2(sv[j]);
            float ta = tanhf(f.x), tb = tanhf(f.y);
            fma2_acc(acc2, pack2(ta, tb), hp[j]);
            c8[j] = f2_to_fp8x2(ta, tb);
        }
    }

    // Store 16 e4m3 tanh values (one STG.128, e-indexed => fully coalesced).
    uint4 st;
    st.x = (uint32_t)c8[0] | ((uint32_t)c8[1] << 16);
    st.y = (uint32_t)c8[2] | ((uint32_t)c8[3] << 16);
    st.z = (uint32_t)c8[4] | ((uint32_t)c8[5] << 16);
    st.w = (uint32_t)c8[6] | ((uint32_t)c8[7] << 16);
    *(uint4*)(g_A8 + (size_t)e * 256 + s * 16) = st;

    float ra, rb2;
    unpack2(acc2, ra, rb2);
    float res = fmaf(sc, ra + rb2, rsv);
    atomicAdd(&g_s1[nbr * 16 + s], res);
}

// ---------------------------------------------------------------------------
// Step 3: s1 -> s2, streaming precomputed e4m3 tanh values from g_A8.
// No tanh, no range check — just dequant + matvec.
// ---------------------------------------------------------------------------
static __global__ __launch_bounds__(256, 6)
void k_prop_stream(const int* __restrict__ Xn, const int* __restrict__ Xe,
                   const int* __restrict__ dg, int E)
{
    int idx = blockIdx.x * 256 + threadIdx.x;
    int e = idx >> 4, s = idx & 15;
    if (e >= E) return;

    const int src = __ldg(&Xn[e]);
    const int nbr = __ldg(&Xe[e]);

    const uint4 au = __ldg((const uint4*)(g_A8 + (size_t)e * 256 + s * 16));
    const float h   = __ldg(&g_s1[src * 16 + s]);
    const float rsv = __ldg(&g_R[src * 16 + s]);
    const float sc  = __fdividef(0.05625f, (float)__ldg(&dg[e]));

    u64t hp[8];
    #pragma unroll
    for (int j = 0; j < 8; ++j) {
        float ha = __shfl_sync(0xffffffffu, h, 2 * j,     16);
        float hb = __shfl_sync(0xffffffffu, h, 2 * j + 1, 16);
        hp[j] = pack2(ha, hb);
    }

    const uint32_t aw[4] = { au.x, au.y, au.z, au.w };
    u64t acc2 = 0ull;
    #pragma unroll
    for (int w = 0; w < 4; ++w) {
        float2 f0 = __half22float2(fp8x2_to_h2((unsigned short)(aw[w] & 0xFFFFu)));
        float2 f1 = __half22float2(fp8x2_to_h2((unsigned short)(aw[w] >> 16)));
        fma2_acc(acc2, pack2(f0.x, f0.y), hp[2 * w]);
        fma2_acc(acc2, pack2(f1.x, f1.y), hp[2 * w + 1]);
    }

    float ra, rb2;
    unpack2(acc2, ra, rb2);
    float res = fmaf(sc, ra + rb2, rsv);
    atomicAdd(&g_s2[nbr * 16 + s], res);
}

// ---------------------------------------------------------------------------
// Readout: logits = concat(emb, s2) @ lin_w + lin_b, softmax.  Warp/node.
// ---------------------------------------------------------------------------
static __global__ __launch_bounds__(256)
void k_final(const float* __restrict__ emb, const float* __restrict__ lw,
             const float* __restrict__ lb, float* __restrict__ out, int V)
{
    int v = (blockIdx.x * blockDim.x + threadIdx.x) >> 5;
    int lane = threadIdx.x & 31;
    if (v >= V) return;
    float p0 = 0.f, p1 = 0.f, p2 = 0.f;
    #pragma unroll
    for (int m = 0; m < 4; ++m) {
        int row = lane + 32 * m;
        float f = __ldg(&emb[(size_t)v * 128 + row]);
        p0 = fmaf(f, __ldg(&lw[row * 3 + 0]), p0);
        p1 = fmaf(f, __ldg(&lw[row * 3 + 1]), p1);
        p2 = fmaf(f, __ldg(&lw[row * 3 + 2]), p2);
    }
    if (lane < 16) {
        float sv = g_s2[v * 16 + lane];
        int row = 128 + lane;
        p0 = fmaf(sv, __ldg(&lw[row * 3 + 0]), p0);
        p1 = fmaf(sv, __ldg(&lw[row * 3 + 1]), p1);
        p2 = fmaf(sv, __ldg(&lw[row * 3 + 2]), p2);
    }
    #pragma unroll
    for (int off = 16; off > 0; off >>= 1) {
        p0 += __shfl_xor_sync(0xffffffffu, p0, off);
        p1 += __shfl_xor_sync(0xffffffffu, p1, off);
        p2 += __shfl_xor_sync(0xffffffffu, p2, off);
    }
    if (lane == 0) {
        p0 += __ldg(&lb[0]); p1 += __ldg(&lb[1]); p2 += __ldg(&lb[2]);
        float mx = fmaxf(p0, fmaxf(p1, p2));
        float e0 = expf(p0 - mx), e1 = expf(p1 - mx), e2 = expf(p2 - mx);
        float inv = 1.f / (e0 + e1 + e2);
        out[(size_t)v * 3 + 0] = e0 * inv;
        out[(size_t)v * 3 + 1] = e1 * inv;
        out[(size_t)v * 3 + 2] = e2 * inv;
    }
}

// ---------------------------------------------------------------------------
extern "C" void kernel_launch(void* const* d_in, const int* in_sizes, int n_in,
                              void* d_out, int out_size)
{
    const int*   X_Node = (const int*)  d_in[0];
    const int*   X_Neis = (const int*)  d_in[1];
    const int*   dg     = (const int*)  d_in[2];
    const float* emb    = (const float*)d_in[3];
    const float* xi_w   = (const float*)d_in[4];
    const float* xi_b   = (const float*)d_in[5];
    const float* rou_w  = (const float*)d_in[6];
    const float* rou_b  = (const float*)d_in[7];
    const float* lin_w  = (const float*)d_in[8];
    const float* lin_b  = (const float*)d_in[9];
    float* out = (float*)d_out;
    const int E = in_sizes[0];
    const int V = in_sizes[3] / 128;

    const int NG = (V + 63) / 64;
    const int pb = (E * 16 + 255) / 256;
    const int np = (V * 64 + 16384 + 255) / 256;

    // Prep: fp16 emb + fragment-ordered fp16 xi_w.
    k_prep<<<np, 256>>>(emb, xi_w, V);
    // K1: tensor-core node GEMM (P/Q fp8) + R table + zero s0/s1/s2.
    k_pre<<<2 * NG + NZB, 256>>>(emb, xi_b, rou_w, rou_b, V, NG);
    // step 1 (states=0 => H=R[src]): scatter into s0 (v4 reductions)
    k_prop_first<<<(E * 4 + 255) / 256, 256>>>(X_Node, X_Neis, E);
    // step 2: s0 -> s1, computing tanh once and materializing A8
    k_prop_store<<<pb, 256>>>(X_Node, X_Neis, dg, E);
    // step 3: s1 -> s2, streaming A8
    k_prop_stream<<<pb, 256>>>(X_Node, X_Neis, dg, E);
    // readout from s2
    k_final<<<(V + 7) / 8, 256>>>(emb, lin_w, lin_b, out, V);
}